// round 6
// baseline (speedup 1.0000x reference)
#include <cuda_runtime.h>

#define NNODES 100000
#define NEDGES 1600000
#define NREL 4

// Scratch. S buffers are CHUNK-MAJOR: S[(r*(DIN/4)+c4)*n + node] as float4 —
// coalesced combine reads (consecutive nodes = consecutive 16B).
__device__ __align__(16) float g_S1[NREL * NNODES * 16];  // 25.6 MB
__device__ __align__(16) float g_S2[NREL * NNODES * 16];  // 25.6 MB
__device__ __align__(16) float g_S3[NREL * NNODES * 32];  // 51.2 MB
__device__ int   g_cnt[NREL * NNODES];                    // 1.6 MB
__device__ __align__(16) float g_h1[NNODES * 16];
__device__ __align__(16) float g_h2[NNODES * 32];

typedef unsigned long long ull;

__device__ __forceinline__ void ffma2(ull& acc, ull a, ull b) {
    asm("fma.rn.f32x2 %0, %1, %2, %0;" : "+l"(acc) : "l"(a), "l"(b));
}
__device__ __forceinline__ ull bcast2(float v) {
    ull r;
    unsigned int u = __float_as_uint(v);
    asm("mov.b64 %0, {%1, %1};" : "=l"(r) : "r"(u));
    return r;
}

// ---------------------------------------------------------------------------
// Scatter: S[(r*CH+c)*n + dst] += h[src, c*4..] via RED.v4 (chunk-major S).
// Gather side reads contiguous node-major h rows (coalesced per edge).
// ---------------------------------------------------------------------------
template <int DIN, bool COUNT>
__global__ void scatter_kernel(const float* __restrict__ h,
                               const int* __restrict__ src,
                               const int* __restrict__ dst,
                               const int* __restrict__ et,
                               float* __restrict__ S,
                               int* __restrict__ cnt, int n, int e) {
    constexpr int CH = DIN / 4;
    int t = blockIdx.x * blockDim.x + threadIdx.x;
    int ed = t / CH;
    int c  = t - ed * CH;
    if (ed >= e) return;
    int s = __ldg(src + ed);
    int d = __ldg(dst + ed);
    int r = __ldg(et + ed);
    const float4 v = *reinterpret_cast<const float4*>(h + (size_t)s * DIN + c * 4);
    float* p = S + ((size_t)(r * CH + c) * n + d) * 4;
    asm volatile("red.global.add.v4.f32 [%0], {%1,%2,%3,%4};"
                 :: "l"(p), "f"(v.x), "f"(v.y), "f"(v.z), "f"(v.w)
                 : "memory");
    if (COUNT && c == 0) atomicAdd(cnt + r * n + d, 1);
}

// ---------------------------------------------------------------------------
// Combine: out[i] = bias + x[i]@root + sum_r (S_r,i/max(cnt,1)) @ W_r
// S is chunk-major -> coalesced warp loads. Weights staged in smem, batched
// broadcast LDS.128. Thread = (2 nodes, 8-col slice), f32x2 accumulators.
// ---------------------------------------------------------------------------
template <int DIN, int DOUT, bool RELU>
__global__ void __launch_bounds__(256)
combine_kernel(const float* __restrict__ xin,   // [n, DIN] node-major
               const float4* __restrict__ S4,   // chunk-major
               const int* __restrict__ cnt,
               const float* __restrict__ W,     // [R, DIN, DOUT]
               const float* __restrict__ root,  // [DIN, DOUT]
               const float* __restrict__ bias,  // [DOUT]
               float* __restrict__ out, int n) {
    constexpr int COLS  = 8;
    constexpr int SPLIT = DOUT / COLS;     // threads per node
    constexpr int NT    = 2;               // nodes per thread
    constexpr int NG    = 256 / SPLIT;     // node-groups per block
    constexpr int NPB   = NG * NT;         // nodes per block
    constexpr int CH    = DIN / 4;
    constexpr int NC4   = 5 * CH;          // 4-row blocks (x + 4 relations)

    __shared__ __align__(16) float sw[5 * DIN * DOUT];
    const int tid = threadIdx.x;
    {
        const float4* r4 = reinterpret_cast<const float4*>(root);
        const float4* w4 = reinterpret_cast<const float4*>(W);
        float4* s4 = reinterpret_cast<float4*>(sw);
        for (int i = tid; i < DIN * DOUT / 4; i += 256) s4[i] = __ldg(r4 + i);
        for (int i = tid; i < NREL * DIN * DOUT / 4; i += 256)
            s4[DIN * DOUT / 4 + i] = __ldg(w4 + i);
    }

    const int ng = tid / SPLIT;
    const int sp = tid % SPLIT;
    const int nbase = blockIdx.x * NPB + ng;

    int nodev[NT];
    bool valid[NT];
    float sc[NT][5];
#pragma unroll
    for (int i = 0; i < NT; i++) {
        int nd = nbase + i * NG;
        valid[i] = nd < n;
        nodev[i] = valid[i] ? nd : 0;
        sc[i][0] = 1.0f;
#pragma unroll
        for (int r = 0; r < NREL; r++) {
            int c = __ldg(cnt + r * n + nodev[i]);
            sc[i][r + 1] = 1.0f / (float)(c > 1 ? c : 1);
        }
    }
    __syncthreads();

    ull acc[NT][4];
    {
        const ull* bb = reinterpret_cast<const ull*>(bias + sp * COLS);
#pragma unroll
        for (int i = 0; i < NT; i++)
#pragma unroll
            for (int j = 0; j < 4; j++) acc[i][j] = bb[j];
    }

    const float* wbase = sw + sp * COLS;
    const float4* x4 = reinterpret_cast<const float4*>(xin);

    float4 vcur[NT], vnxt[NT];
#pragma unroll
    for (int i = 0; i < NT; i++)
        vcur[i] = __ldg(x4 + (size_t)nodev[i] * CH);  // (rb=0, c4=0)

#pragma unroll
    for (int b = 0; b < NC4; b++) {
        const int rb = b / CH;
        const int c4 = b % CH;
        // Prefetch next block's inputs. rb==0: node-major x. rb>0: chunk-major
        // S -> warp-coalesced (consecutive nodes, consecutive 16B).
        if (b + 1 < NC4) {
            const int bn  = b + 1;
            const int rbn = bn / CH;
            const int c4n = bn % CH;
#pragma unroll
            for (int i = 0; i < NT; i++) {
                if (rbn == 0)
                    vnxt[i] = __ldg(x4 + (size_t)nodev[i] * CH + c4n);
                else
                    vnxt[i] = __ldg(S4 + (size_t)((rbn - 1) * CH + c4n) * n
                                       + nodev[i]);
            }
        }
        // Batch all 8 weight LDS.128 for this 4-row block
        ulonglong2 w[4][2];
#pragma unroll
        for (int k = 0; k < 4; k++) {
            const ulonglong2* wp = reinterpret_cast<const ulonglong2*>(
                wbase + (rb * DIN + c4 * 4 + k) * DOUT);
            w[k][0] = wp[0];
            w[k][1] = wp[1];
        }
        float vs[NT][4];
#pragma unroll
        for (int i = 0; i < NT; i++) {
            const float s0 = sc[i][rb];
            vs[i][0] = vcur[i].x * s0;
            vs[i][1] = vcur[i].y * s0;
            vs[i][2] = vcur[i].z * s0;
            vs[i][3] = vcur[i].w * s0;
        }
#pragma unroll
        for (int k = 0; k < 4; k++) {
#pragma unroll
            for (int i = 0; i < NT; i++) {
                const ull v2 = bcast2(vs[i][k]);
                ffma2(acc[i][0], v2, w[k][0].x);
                ffma2(acc[i][1], v2, w[k][0].y);
                ffma2(acc[i][2], v2, w[k][1].x);
                ffma2(acc[i][3], v2, w[k][1].y);
            }
        }
#pragma unroll
        for (int i = 0; i < NT; i++) vcur[i] = vnxt[i];
    }

#pragma unroll
    for (int i = 0; i < NT; i++) {
        if (!valid[i]) continue;
        float* op = out + (size_t)nodev[i] * DOUT + sp * COLS;
#pragma unroll
        for (int j = 0; j < 4; j++) {
            float2 f = *reinterpret_cast<float2*>(&acc[i][j]);
            if (RELU) {
                f.x = fmaxf(f.x, 0.0f);
                f.y = fmaxf(f.y, 0.0f);
            }
            reinterpret_cast<float2*>(op)[j] = f;
        }
    }
}

// ---------------------------------------------------------------------------
// Launcher: memsets -> (scatter[+count], combine) x 3 layers
// ---------------------------------------------------------------------------
extern "C" void kernel_launch(void* const* d_in, const int* in_sizes, int n_in,
                              void* d_out, int out_size) {
    const float* x     = (const float*)d_in[0];
    const int*   ei    = (const int*)d_in[1];   // [2, E]: src then dst
    const int*   et    = (const int*)d_in[2];
    const float* W1    = (const float*)d_in[3];
    const float* root1 = (const float*)d_in[4];
    const float* b1    = (const float*)d_in[5];
    const float* W2    = (const float*)d_in[6];
    const float* root2 = (const float*)d_in[7];
    const float* b2    = (const float*)d_in[8];
    const float* W3    = (const float*)d_in[9];
    const float* root3 = (const float*)d_in[10];
    const float* b3    = (const float*)d_in[11];
    float* out = (float*)d_out;

    const int n = in_sizes[0] / 16;
    const int e = in_sizes[2];
    const int* src = ei;
    const int* dst = ei + e;

    float *pS1, *pS2, *pS3, *ph1, *ph2;
    int* pcnt;
    cudaGetSymbolAddress((void**)&pS1, g_S1);
    cudaGetSymbolAddress((void**)&pS2, g_S2);
    cudaGetSymbolAddress((void**)&pS3, g_S3);
    cudaGetSymbolAddress((void**)&pcnt, g_cnt);
    cudaGetSymbolAddress((void**)&ph1, g_h1);
    cudaGetSymbolAddress((void**)&ph2, g_h2);

    cudaMemsetAsync(pS1, 0, sizeof(float) * NREL * NNODES * 16);
    cudaMemsetAsync(pS2, 0, sizeof(float) * NREL * NNODES * 16);
    cudaMemsetAsync(pS3, 0, sizeof(float) * NREL * NNODES * 32);
    cudaMemsetAsync(pcnt, 0, sizeof(int) * NREL * NNODES);

    const int TB = 256;

    // Layer 1: 16 -> 16, relu. NPB = 256
    {
        int tot = e * 4;
        scatter_kernel<16, true><<<(tot + TB - 1) / TB, TB>>>(
            x, src, dst, et, pS1, pcnt, n, e);
        combine_kernel<16, 16, true><<<(n + 255) / 256, 256>>>(
            x, (const float4*)pS1, pcnt, W1, root1, b1, ph1, n);
    }

    // Layer 2: 16 -> 32, relu. NPB = 128
    {
        int tot = e * 4;
        scatter_kernel<16, false><<<(tot + TB - 1) / TB, TB>>>(
            ph1, src, dst, et, pS2, pcnt, n, e);
        combine_kernel<16, 32, true><<<(n + 127) / 128, 256>>>(
            ph1, (const float4*)pS2, pcnt, W2, root2, b2, ph2, n);
    }

    // Layer 3: 32 -> 64, no relu. NPB = 64
    {
        int tot = e * 8;
        scatter_kernel<32, false><<<(tot + TB - 1) / TB, TB>>>(
            ph2, src, dst, et, pS3, pcnt, n, e);
        combine_kernel<32, 64, false><<<(n + 63) / 64, 256>>>(
            ph2, (const float4*)pS3, pcnt, W3, root3, b3, out, n);
    }
}

// round 7
// speedup vs baseline: 1.1645x; 1.1645x over previous
#include <cuda_runtime.h>

#define NNODES 100000
#define NEDGES 1600000
#define NREL 4

// Scratch (node-major S: S[r][node][DIN]) — contiguous per (r,dst) row so one
// edge's 4 RED.v4 land in one 64/128B region.
__device__ __align__(16) float g_S1[NREL * NNODES * 16];  // 25.6 MB
__device__ __align__(16) float g_S2[NREL * NNODES * 16];  // 25.6 MB
__device__ __align__(16) float g_S3[NREL * NNODES * 32];  // 51.2 MB
__device__ int   g_cnt[NREL * NNODES];                    // 1.6 MB
__device__ __align__(16) float g_h1[NNODES * 16];
__device__ __align__(16) float g_h2[NNODES * 32];

typedef unsigned long long ull;

__device__ __forceinline__ void ffma2(ull& acc, ull a, ull b) {
    asm("fma.rn.f32x2 %0, %1, %2, %0;" : "+l"(acc) : "l"(a), "l"(b));
}
__device__ __forceinline__ ull bcast2(float v) {
    ull r;
    unsigned int u = __float_as_uint(v);
    asm("mov.b64 %0, {%1, %1};" : "=l"(r) : "r"(u));
    return r;
}

// ---------------------------------------------------------------------------
// Scatter: S[r, dst, :] += h[src, :] via RED.v4 (node-major S).
// ---------------------------------------------------------------------------
template <int DIN, bool COUNT>
__global__ void scatter_kernel(const float* __restrict__ h,
                               const int* __restrict__ src,
                               const int* __restrict__ dst,
                               const int* __restrict__ et,
                               float* __restrict__ S,
                               int* __restrict__ cnt, int n, int e) {
    constexpr int CH = DIN / 4;
    int t = blockIdx.x * blockDim.x + threadIdx.x;
    int ed = t / CH;
    int c  = t - ed * CH;
    if (ed >= e) return;
    int s = __ldg(src + ed);
    int d = __ldg(dst + ed);
    int r = __ldg(et + ed);
    const float4 v = *reinterpret_cast<const float4*>(h + (size_t)s * DIN + c * 4);
    float* p = S + ((size_t)r * n + d) * DIN + c * 4;
    asm volatile("red.global.add.v4.f32 [%0], {%1,%2,%3,%4};"
                 :: "l"(p), "f"(v.x), "f"(v.y), "f"(v.z), "f"(v.w)
                 : "memory");
    if (COUNT && c == 0) atomicAdd(cnt + r * n + d, 1);
}

// ---------------------------------------------------------------------------
// Combine (PERSISTENT): out[i] = bias + x[i]@root + sum_r (S_r,i/cnt) @ W_r
// Fixed small grid; weights staged into smem ONCE per block, then grid-stride
// over node tiles. Inner body: batched broadcast LDS.128, NT=2 nodes/thread,
// f32x2 accumulators, 1-block LDG prefetch.
// ---------------------------------------------------------------------------
template <int DIN, int DOUT, bool RELU>
__global__ void __launch_bounds__(256)
combine_kernel(const float* __restrict__ xin,   // [n, DIN]
               const float* __restrict__ S,     // [R, n, DIN]
               const int* __restrict__ cnt,
               const float* __restrict__ W,     // [R, DIN, DOUT]
               const float* __restrict__ root,  // [DIN, DOUT]
               const float* __restrict__ bias,  // [DOUT]
               float* __restrict__ out, int n) {
    constexpr int COLS  = 8;
    constexpr int SPLIT = DOUT / COLS;     // threads per node
    constexpr int NT    = 2;               // nodes per thread
    constexpr int NG    = 256 / SPLIT;     // node-groups per block
    constexpr int NPB   = NG * NT;         // nodes per tile
    constexpr int CH    = DIN / 4;
    constexpr int NC4   = 5 * CH;          // 4-row blocks (x + 4 relations)

    __shared__ __align__(16) float sw[5 * DIN * DOUT];
    const int tid = threadIdx.x;
    {   // stage weights ONCE per block
        const float4* r4 = reinterpret_cast<const float4*>(root);
        const float4* w4 = reinterpret_cast<const float4*>(W);
        float4* s4 = reinterpret_cast<float4*>(sw);
        for (int i = tid; i < DIN * DOUT / 4; i += 256) s4[i] = __ldg(r4 + i);
        for (int i = tid; i < NREL * DIN * DOUT / 4; i += 256)
            s4[DIN * DOUT / 4 + i] = __ldg(w4 + i);
    }
    __syncthreads();

    const int ng = tid / SPLIT;
    const int sp = tid % SPLIT;
    const float* wbase = sw + sp * COLS;
    const float4* x4 = reinterpret_cast<const float4*>(xin);
    const ull* bb = reinterpret_cast<const ull*>(bias + sp * COLS);

    for (int tile = blockIdx.x * NPB; tile < n; tile += gridDim.x * NPB) {
        int nodev[NT];
        bool valid[NT];
        float sc[NT][5];
#pragma unroll
        for (int i = 0; i < NT; i++) {
            int nd = tile + ng + i * NG;
            valid[i] = nd < n;
            nodev[i] = valid[i] ? nd : 0;
            sc[i][0] = 1.0f;
#pragma unroll
            for (int r = 0; r < NREL; r++) {
                int c = __ldg(cnt + r * n + nodev[i]);
                sc[i][r + 1] = 1.0f / (float)(c > 1 ? c : 1);
            }
        }

        ull acc[NT][4];
#pragma unroll
        for (int i = 0; i < NT; i++)
#pragma unroll
            for (int j = 0; j < 4; j++) acc[i][j] = bb[j];

        float4 vcur[NT], vnxt[NT];
#pragma unroll
        for (int i = 0; i < NT; i++)
            vcur[i] = __ldg(x4 + (size_t)nodev[i] * CH);

#pragma unroll
        for (int b = 0; b < NC4; b++) {
            const int rb = b / CH;
            const int c4 = b % CH;
            if (b + 1 < NC4) {
                const int rbn = (b + 1) / CH;
                const int c4n = (b + 1) % CH;
#pragma unroll
                for (int i = 0; i < NT; i++) {
                    const float* base = (rbn == 0)
                        ? xin + (size_t)nodev[i] * DIN
                        : S + ((size_t)(rbn - 1) * n + nodev[i]) * DIN;
                    vnxt[i] = __ldg(reinterpret_cast<const float4*>(base) + c4n);
                }
            }
            ulonglong2 w[4][2];
#pragma unroll
            for (int k = 0; k < 4; k++) {
                const ulonglong2* wp = reinterpret_cast<const ulonglong2*>(
                    wbase + (rb * DIN + c4 * 4 + k) * DOUT);
                w[k][0] = wp[0];
                w[k][1] = wp[1];
            }
            float vs[NT][4];
#pragma unroll
            for (int i = 0; i < NT; i++) {
                const float s0 = sc[i][rb];
                vs[i][0] = vcur[i].x * s0;
                vs[i][1] = vcur[i].y * s0;
                vs[i][2] = vcur[i].z * s0;
                vs[i][3] = vcur[i].w * s0;
            }
#pragma unroll
            for (int k = 0; k < 4; k++) {
#pragma unroll
                for (int i = 0; i < NT; i++) {
                    const ull v2 = bcast2(vs[i][k]);
                    ffma2(acc[i][0], v2, w[k][0].x);
                    ffma2(acc[i][1], v2, w[k][0].y);
                    ffma2(acc[i][2], v2, w[k][1].x);
                    ffma2(acc[i][3], v2, w[k][1].y);
                }
            }
#pragma unroll
            for (int i = 0; i < NT; i++) vcur[i] = vnxt[i];
        }

#pragma unroll
        for (int i = 0; i < NT; i++) {
            if (!valid[i]) continue;
            float* op = out + (size_t)nodev[i] * DOUT + sp * COLS;
#pragma unroll
            for (int j = 0; j < 4; j++) {
                float2 f = *reinterpret_cast<float2*>(&acc[i][j]);
                if (RELU) {
                    f.x = fmaxf(f.x, 0.0f);
                    f.y = fmaxf(f.y, 0.0f);
                }
                reinterpret_cast<float2*>(op)[j] = f;
            }
        }
    }
}

// ---------------------------------------------------------------------------
// Launcher: memsets -> (scatter[+count], combine) x 3 layers
// ---------------------------------------------------------------------------
extern "C" void kernel_launch(void* const* d_in, const int* in_sizes, int n_in,
                              void* d_out, int out_size) {
    const float* x     = (const float*)d_in[0];
    const int*   ei    = (const int*)d_in[1];   // [2, E]: src then dst
    const int*   et    = (const int*)d_in[2];
    const float* W1    = (const float*)d_in[3];
    const float* root1 = (const float*)d_in[4];
    const float* b1    = (const float*)d_in[5];
    const float* W2    = (const float*)d_in[6];
    const float* root2 = (const float*)d_in[7];
    const float* b2    = (const float*)d_in[8];
    const float* W3    = (const float*)d_in[9];
    const float* root3 = (const float*)d_in[10];
    const float* b3    = (const float*)d_in[11];
    float* out = (float*)d_out;

    const int n = in_sizes[0] / 16;
    const int e = in_sizes[2];
    const int* src = ei;
    const int* dst = ei + e;

    float *pS1, *pS2, *pS3, *ph1, *ph2;
    int* pcnt;
    cudaGetSymbolAddress((void**)&pS1, g_S1);
    cudaGetSymbolAddress((void**)&pS2, g_S2);
    cudaGetSymbolAddress((void**)&pS3, g_S3);
    cudaGetSymbolAddress((void**)&pcnt, g_cnt);
    cudaGetSymbolAddress((void**)&ph1, g_h1);
    cudaGetSymbolAddress((void**)&ph2, g_h2);

    cudaMemsetAsync(pS1, 0, sizeof(float) * NREL * NNODES * 16);
    cudaMemsetAsync(pS2, 0, sizeof(float) * NREL * NNODES * 16);
    cudaMemsetAsync(pS3, 0, sizeof(float) * NREL * NNODES * 32);
    cudaMemsetAsync(pcnt, 0, sizeof(int) * NREL * NNODES);

    const int TB = 256;
    const int CGRID = 148 * 3;   // persistent-ish: 3 blocks/SM

    // Layer 1: 16 -> 16, relu. Scatter fuses degree count.
    {
        int tot = e * 4;
        scatter_kernel<16, true><<<(tot + TB - 1) / TB, TB>>>(
            x, src, dst, et, pS1, pcnt, n, e);
        combine_kernel<16, 16, true><<<CGRID, 256>>>(
            x, pS1, pcnt, W1, root1, b1, ph1, n);
    }

    // Layer 2: 16 -> 32, relu
    {
        int tot = e * 4;
        scatter_kernel<16, false><<<(tot + TB - 1) / TB, TB>>>(
            ph1, src, dst, et, pS2, pcnt, n, e);
        combine_kernel<16, 32, true><<<CGRID, 256>>>(
            ph1, pS2, pcnt, W2, root2, b2, ph2, n);
    }

    // Layer 3: 32 -> 64, no relu
    {
        int tot = e * 8;
        scatter_kernel<32, false><<<(tot + TB - 1) / TB, TB>>>(
            ph2, src, dst, et, pS3, pcnt, n, e);
        combine_kernel<32, 64, false><<<CGRID, 256>>>(
            ph2, pS3, pcnt, W3, root3, b3, out, n);
    }
}